// round 5
// baseline (speedup 1.0000x reference)
#include <cuda_runtime.h>
#include <cuda_bf16.h>
#include <math.h>
#include <stdint.h>

// ---------------------------------------------------------------------------
// B=2, T=24, H=256, W=256, N=512, HIDDEN=256
// conv1: 7x7x3->64 s2 (pad_lo=2) -> 128x128  fp32 direct, epilogue splits bf16
// conv2: 3x3x64->128 s2          -> 64x64    mma.sync bf16x3, cp.async fill
// conv3: 3x3x128->256 s2         -> 32x32    mma.sync bf16x3, cp.async fill
// corr : [48] 512x1024x256 GEMM              mma.sync bf16x3, cp.async fill
// ---------------------------------------------------------------------------

__device__ __nv_bfloat16 g_f1h[2 * 24 * 128 * 128 * 64];   // 100 MB
__device__ __nv_bfloat16 g_f1l[2 * 24 * 128 * 128 * 64];   // 100 MB
__device__ __nv_bfloat16 g_f2h[2 * 24 * 64 * 64 * 128];    //  50 MB
__device__ __nv_bfloat16 g_f2l[2 * 24 * 64 * 64 * 128];    //  50 MB
__device__ float         g_feat3[2 * 24 * 32 * 32 * 256];  //  50 MB (for sampling)
__device__ __nv_bfloat16 g_f3h[2 * 24 * 32 * 32 * 256];    //  25 MB
__device__ __nv_bfloat16 g_f3l[2 * 24 * 32 * 32 * 256];    //  25 MB
__device__ __nv_bfloat16 g_qh[2 * 512 * 256];
__device__ __nv_bfloat16 g_ql[2 * 512 * 256];
__device__ float         g_corr[2 * 24 * 512 * 1024];      // 100 MB
__device__ __nv_bfloat16 g_wt2h[128 * 576],  g_wt2l[128 * 576];
__device__ __nv_bfloat16 g_wt3h[256 * 1152], g_wt3l[256 * 1152];

// ---------------------------------------------------------------------------
// helpers
// ---------------------------------------------------------------------------
__device__ __forceinline__ uint32_t smem_u32(const void* p) {
    uint32_t a;
    asm("{ .reg .u64 t; cvta.to.shared.u64 t, %1; cvt.u32.u64 %0, t; }"
        : "=r"(a) : "l"(p));
    return a;
}

__device__ __forceinline__ void cp16(uint32_t dst, const void* gsrc, uint32_t ss) {
    asm volatile(
        "{ .reg .u64 g; cvta.to.global.u64 g, %1;"
        "  cp.async.ca.shared.global [%0], [g], 16, %2; }"
        :: "r"(dst), "l"(gsrc), "r"(ss) : "memory");
}
#define CP_COMMIT() asm volatile("cp.async.commit_group;" ::: "memory")
#define CP_WAIT1()  asm volatile("cp.async.wait_group 1;" ::: "memory")
#define CP_WAIT0()  asm volatile("cp.async.wait_group 0;" ::: "memory")

__device__ __forceinline__ void ldmx4(uint32_t* r, uint32_t addr) {
    asm volatile(
        "ldmatrix.sync.aligned.m8n8.x4.shared.b16 {%0,%1,%2,%3}, [%4];"
        : "=r"(r[0]), "=r"(r[1]), "=r"(r[2]), "=r"(r[3]) : "r"(addr));
}

__device__ __forceinline__ void mma_bf16(float* d, const uint32_t* a,
                                         const uint32_t* b) {
    asm volatile(
        "mma.sync.aligned.m16n8k16.row.col.f32.bf16.bf16.f32 "
        "{%0,%1,%2,%3}, {%4,%5,%6,%7}, {%8,%9}, {%0,%1,%2,%3};"
        : "+f"(d[0]), "+f"(d[1]), "+f"(d[2]), "+f"(d[3])
        : "r"(a[0]), "r"(a[1]), "r"(a[2]), "r"(a[3]), "r"(b[0]), "r"(b[1]));
}

__device__ __forceinline__ uint32_t pack_h(float a, float b) {
    __nv_bfloat162 t = __floats2bfloat162_rn(a, b);
    return *reinterpret_cast<uint32_t*>(&t);
}
__device__ __forceinline__ uint32_t pack_l(float a, float b, uint32_t h) {
    __nv_bfloat162 th = *reinterpret_cast<__nv_bfloat162*>(&h);
    return pack_h(a - __bfloat162float(th.x), b - __bfloat162float(th.y));
}

// split one float4 into bf16-hi (8B) and bf16-lo (8B)
__device__ __forceinline__ void split_store(char* hi, char* lo, float4 v) {
    __nv_bfloat162 h01 = __floats2bfloat162_rn(v.x, v.y);
    __nv_bfloat162 h23 = __floats2bfloat162_rn(v.z, v.w);
    float hx = __bfloat162float(h01.x), hy = __bfloat162float(h01.y);
    float hz = __bfloat162float(h23.x), hw = __bfloat162float(h23.y);
    __nv_bfloat162 l01 = __floats2bfloat162_rn(v.x - hx, v.y - hy);
    __nv_bfloat162 l23 = __floats2bfloat162_rn(v.z - hz, v.w - hw);
    uint2 hv = make_uint2(*reinterpret_cast<uint32_t*>(&h01),
                          *reinterpret_cast<uint32_t*>(&h23));
    uint2 lv = make_uint2(*reinterpret_cast<uint32_t*>(&l01),
                          *reinterpret_cast<uint32_t*>(&l23));
    *reinterpret_cast<uint2*>(hi) = hv;
    *reinterpret_cast<uint2*>(lo) = lv;
}

// smem tile: 128 rows x 32 bf16, row stride 80 B (16B pad -> cf-free ldmatrix)
#define RS   80
#define MATB (128 * RS)      // 10240 B per matrix
#define BUFB (4 * MATB)      // A_hi | A_lo | B_hi | B_lo = 40960 B / stage
#define DSMEM3 (3 * BUFB)    // 3-stage pipeline: 122880 B

// ---------------------------------------------------------------------------
// conv1: 7x7 s2 pad_lo=2, Cin=3, Cout=64 (fp32 FFMA; epilogue -> bf16 hi/lo)
// ---------------------------------------------------------------------------
__global__ void __launch_bounds__(128) conv1_kernel(
    const float* __restrict__ video,
    const float* __restrict__ w,
    const float* __restrict__ bias)
{
    __shared__ float sw[7 * 7 * 3 * 64 + 64];
    for (int i = threadIdx.x; i < 7 * 7 * 3 * 64; i += 128) sw[i] = w[i];
    if (threadIdx.x < 64) sw[9408 + threadIdx.x] = bias[threadIdx.x];
    __syncthreads();

    int p  = blockIdx.x * 128 + threadIdx.x;
    int x  = p & 127;
    int y  = (p >> 7) & 127;
    int bt = p >> 14;

    float acc[64];
#pragma unroll
    for (int c = 0; c < 64; c++) acc[c] = sw[9408 + c];

    const float* vb = video + (size_t)bt * (256 * 256 * 3);
    const float inv255 = 1.0f / 255.0f;

#pragma unroll 1
    for (int dy = 0; dy < 7; dy++) {
        int iy = 2 * y + dy - 2;
        if ((unsigned)iy >= 256u) continue;
#pragma unroll 1
        for (int dx = 0; dx < 7; dx++) {
            int ix = 2 * x + dx - 2;
            if ((unsigned)ix >= 256u) continue;
            const float* vp = vb + ((size_t)iy * 256 + ix) * 3;
#pragma unroll
            for (int ci = 0; ci < 3; ci++) {
                float v = vp[ci] * inv255;
                const float4* w4 =
                    reinterpret_cast<const float4*>(&sw[((dy * 7 + dx) * 3 + ci) * 64]);
#pragma unroll
                for (int k = 0; k < 16; k++) {
                    float4 wv = w4[k];
                    acc[4 * k + 0] = fmaf(v, wv.x, acc[4 * k + 0]);
                    acc[4 * k + 1] = fmaf(v, wv.y, acc[4 * k + 1]);
                    acc[4 * k + 2] = fmaf(v, wv.z, acc[4 * k + 2]);
                    acc[4 * k + 3] = fmaf(v, wv.w, acc[4 * k + 3]);
                }
            }
        }
    }

#pragma unroll
    for (int k = 0; k < 16; k++) {
        float4 o;
        o.x = fmaxf(acc[4 * k + 0], 0.0f);
        o.y = fmaxf(acc[4 * k + 1], 0.0f);
        o.z = fmaxf(acc[4 * k + 2], 0.0f);
        o.w = fmaxf(acc[4 * k + 3], 0.0f);
        split_store(reinterpret_cast<char*>(&g_f1h[(size_t)p * 64 + 4 * k]),
                    reinterpret_cast<char*>(&g_f1l[(size_t)p * 64 + 4 * k]), o);
    }
}

// ---------------------------------------------------------------------------
// Weight transpose + bf16 split: w[k][cout] -> wth/wtl[cout][k]
// ---------------------------------------------------------------------------
__global__ void transpose_split_w(const float* __restrict__ w,
                                  __nv_bfloat16* __restrict__ h,
                                  __nv_bfloat16* __restrict__ l, int K, int C)
{
    int i = blockIdx.x * 256 + threadIdx.x;
    if (i < K * C) {
        int k = i / C, c = i - k * C;
        float v = w[i];
        __nv_bfloat16 hb = __float2bfloat16(v);
        h[(size_t)c * K + k] = hb;
        l[(size_t)c * K + k] = __float2bfloat16(v - __bfloat162float(hb));
    }
}

// ---------------------------------------------------------------------------
// Implicit-GEMM 3x3 s2 conv, mma.sync bf16 3-pass, cp.async 3-stage pipeline.
// Block tile 128(M px) x 128(N cout), K chunk 32. 8 warps (2M x 4N).
// ---------------------------------------------------------------------------
template <int CIN, int COUT, int HIN, int WIN, int HOUT, int WOUT, bool WF32>
__global__ void __launch_bounds__(256, 1) conv_mma_kernel(
    const __nv_bfloat16* __restrict__ inh,
    const __nv_bfloat16* __restrict__ inl,
    const __nv_bfloat16* __restrict__ wth,
    const __nv_bfloat16* __restrict__ wtl,
    const float* __restrict__ bias,
    __nv_bfloat16* __restrict__ outh,
    __nv_bfloat16* __restrict__ outl,
    float* __restrict__ outf)
{
    extern __shared__ char sm[];
    __shared__ float s_bias[128];

    const int KTOT = 9 * CIN;
    const int CPP  = CIN / 32;
    const int NT   = 9 * CPP;

    int tid  = threadIdx.x;
    int lane = tid & 31;
    int wid  = tid >> 5;
    int wm   = wid & 1;
    int wn   = wid >> 1;
    int cobase = blockIdx.y * 128;

    if (tid < 128) s_bias[tid] = bias[cobase + tid];

    // fill indices: 2 threads per row, 16 bf16 each
    int fr = tid >> 1;
    int fo = (tid & 1) * 16;
    int p  = blockIdx.x * 128 + fr;
    int fx = p % WOUT;
    int fy = (p / WOUT) % HOUT;
    int fbt = p / (WOUT * HOUT);
    const __nv_bfloat16* bsh = wth + (size_t)(cobase + fr) * KTOT + fo;
    const __nv_bfloat16* bsl = wtl + (size_t)(cobase + fr) * KTOT + fo;

    uint32_t smb = smem_u32(sm);

    int aoff = ((((lane >> 3) & 1) * 8 + (lane & 7)) * RS) + ((lane >> 4) * 8) * 2;
    int boff = (((lane >> 4) * 8 + (lane & 7)) * RS) + (((lane >> 3) & 1) * 8) * 2;

    float acc[4][4][4];
#pragma unroll
    for (int i = 0; i < 4; i++)
#pragma unroll
        for (int j = 0; j < 4; j++)
#pragma unroll
            for (int k = 0; k < 4; k++) acc[i][j][k] = 0.0f;

    auto FILL = [&](int s, int kt) {
        int pos = kt / CPP, ci0 = (kt - pos * CPP) * 32;
        int dy = pos / 3, dx = pos - dy * 3;
        int iy = 2 * fy + dy, ix = 2 * fx + dx;
        bool valid = (iy < HIN) && (ix < WIN);
        uint32_t vs = valid ? 16u : 0u;
        size_t asrc = valid
            ? ((((size_t)fbt * HIN + iy) * WIN + ix) * CIN + ci0 + fo) : 0;
        uint32_t d = smb + s * BUFB + fr * RS + fo * 2;
        cp16(d,                 inh + asrc,     vs);
        cp16(d + 16,            inh + asrc + 8, vs);
        cp16(d + MATB,          inl + asrc,     vs);
        cp16(d + MATB + 16,     inl + asrc + 8, vs);
        cp16(d + 2 * MATB,      bsh + kt * 32,     16u);
        cp16(d + 2 * MATB + 16, bsh + kt * 32 + 8, 16u);
        cp16(d + 3 * MATB,      bsl + kt * 32,     16u);
        cp16(d + 3 * MATB + 16, bsl + kt * 32 + 8, 16u);
    };

    auto COMPUTE = [&](int s) {
        uint32_t ab = smb + s * BUFB;
#pragma unroll
        for (int ks = 0; ks < 2; ks++) {
            uint32_t bh[8], bl[8];
#pragma unroll
            for (int q = 0; q < 2; q++) {
                uint32_t baddr = ab + 2 * MATB + boff + (wn * 32 + q * 16) * RS + ks * 32;
                ldmx4(&bh[4 * q], baddr);
                ldmx4(&bl[4 * q], baddr + MATB);
            }
#pragma unroll
            for (int mt = 0; mt < 4; mt++) {
                uint32_t af[4];
                uint32_t aaddr = ab + aoff + (wm * 64 + mt * 16) * RS + ks * 32;
                ldmx4(af, aaddr);
#pragma unroll
                for (int nt = 0; nt < 4; nt++) mma_bf16(acc[mt][nt], af, &bh[2 * nt]);
#pragma unroll
                for (int nt = 0; nt < 4; nt++) mma_bf16(acc[mt][nt], af, &bl[2 * nt]);
                ldmx4(af, aaddr + MATB);
#pragma unroll
                for (int nt = 0; nt < 4; nt++) mma_bf16(acc[mt][nt], af, &bh[2 * nt]);
            }
        }
    };

    FILL(0, 0); CP_COMMIT();
    FILL(1, 1); CP_COMMIT();
#pragma unroll 1
    for (int kt = 0; kt < NT; kt++) {
        int s = kt % 3;
        if (kt + 1 < NT) { CP_WAIT1(); } else { CP_WAIT0(); }
        __syncthreads();
        if (kt + 2 < NT) { FILL((kt + 2) % 3, kt + 2); CP_COMMIT(); }
        COMPUTE(s);
    }

    // epilogue: bias + relu -> bf16 hi/lo (+ optional fp32)
    int mrow = blockIdx.x * 128 + wm * 64 + (lane >> 2);
    int cbase = wn * 32 + 2 * (lane & 3);
#pragma unroll
    for (int mt = 0; mt < 4; mt++) {
#pragma unroll
        for (int nt = 0; nt < 4; nt++) {
            int col = cbase + nt * 8;
            float b0 = s_bias[col], b1 = s_bias[col + 1];
            size_t r0 = (size_t)(mrow + mt * 16) * COUT + cobase + col;
            size_t r1 = (size_t)(mrow + mt * 16 + 8) * COUT + cobase + col;
            float a0 = fmaxf(acc[mt][nt][0] + b0, 0.f);
            float a1 = fmaxf(acc[mt][nt][1] + b1, 0.f);
            float a2 = fmaxf(acc[mt][nt][2] + b0, 0.f);
            float a3 = fmaxf(acc[mt][nt][3] + b1, 0.f);
            uint32_t h0 = pack_h(a0, a1), h1 = pack_h(a2, a3);
            *reinterpret_cast<uint32_t*>(outh + r0) = h0;
            *reinterpret_cast<uint32_t*>(outh + r1) = h1;
            *reinterpret_cast<uint32_t*>(outl + r0) = pack_l(a0, a1, h0);
            *reinterpret_cast<uint32_t*>(outl + r1) = pack_l(a2, a3, h1);
            if (WF32) {
                *reinterpret_cast<float2*>(outf + r0) = make_float2(a0, a1);
                *reinterpret_cast<float2*>(outf + r1) = make_float2(a2, a3);
            }
        }
    }
}

// ---------------------------------------------------------------------------
// corr GEMM: D[bt][n][hw] = Q[b][n][:].X[bt][hw][:] / 16, cp.async pipeline.
// ---------------------------------------------------------------------------
__global__ void __launch_bounds__(256, 1) corr_mma_kernel()
{
    extern __shared__ char sm[];

    int tid  = threadIdx.x;
    int lane = tid & 31;
    int wid  = tid >> 5;
    int wm   = wid & 1;
    int wn   = wid >> 1;

    int bt  = blockIdx.z;
    int b   = bt / 24;
    int n0  = blockIdx.y * 128;
    int hw0 = blockIdx.x * 128;

    int fr = tid >> 1;
    int fo = (tid & 1) * 16;
    const __nv_bfloat16* ah = g_qh + ((size_t)b * 512 + n0 + fr) * 256 + fo;
    const __nv_bfloat16* al = g_ql + ((size_t)b * 512 + n0 + fr) * 256 + fo;
    const __nv_bfloat16* bh_ = g_f3h + ((size_t)bt * 1024 + hw0 + fr) * 256 + fo;
    const __nv_bfloat16* bl_ = g_f3l + ((size_t)bt * 1024 + hw0 + fr) * 256 + fo;

    uint32_t smb = smem_u32(sm);

    int aoff = ((((lane >> 3) & 1) * 8 + (lane & 7)) * RS) + ((lane >> 4) * 8) * 2;
    int boff = (((lane >> 4) * 8 + (lane & 7)) * RS) + (((lane >> 3) & 1) * 8) * 2;

    float acc[4][4][4];
#pragma unroll
    for (int i = 0; i < 4; i++)
#pragma unroll
        for (int j = 0; j < 4; j++)
#pragma unroll
            for (int k = 0; k < 4; k++) acc[i][j][k] = 0.0f;

    auto FILL = [&](int s, int kt) {
        uint32_t d = smb + s * BUFB + fr * RS + fo * 2;
        cp16(d,                 ah + kt * 32,      16u);
        cp16(d + 16,            ah + kt * 32 + 8,  16u);
        cp16(d + MATB,          al + kt * 32,      16u);
        cp16(d + MATB + 16,     al + kt * 32 + 8,  16u);
        cp16(d + 2 * MATB,      bh_ + kt * 32,     16u);
        cp16(d + 2 * MATB + 16, bh_ + kt * 32 + 8, 16u);
        cp16(d + 3 * MATB,      bl_ + kt * 32,     16u);
        cp16(d + 3 * MATB + 16, bl_ + kt * 32 + 8, 16u);
    };

    auto COMPUTE = [&](int s) {
        uint32_t ab = smb + s * BUFB;
#pragma unroll
        for (int ks = 0; ks < 2; ks++) {
            uint32_t bh[8], bl[8];
#pragma unroll
            for (int q = 0; q < 2; q++) {
                uint32_t baddr = ab + 2 * MATB + boff + (wn * 32 + q * 16) * RS + ks * 32;
                ldmx4(&bh[4 * q], baddr);
                ldmx4(&bl[4 * q], baddr + MATB);
            }
#pragma unroll
            for (int mt = 0; mt < 4; mt++) {
                uint32_t af[4];
                uint32_t aaddr = ab + aoff + (wm * 64 + mt * 16) * RS + ks * 32;
                ldmx4(af, aaddr);
#pragma unroll
                for (int nt = 0; nt < 4; nt++) mma_bf16(acc[mt][nt], af, &bh[2 * nt]);
#pragma unroll
                for (int nt = 0; nt < 4; nt++) mma_bf16(acc[mt][nt], af, &bl[2 * nt]);
                ldmx4(af, aaddr + MATB);
#pragma unroll
                for (int nt = 0; nt < 4; nt++) mma_bf16(acc[mt][nt], af, &bh[2 * nt]);
            }
        }
    };

    FILL(0, 0); CP_COMMIT();
    FILL(1, 1); CP_COMMIT();
#pragma unroll 1
    for (int kt = 0; kt < 8; kt++) {
        int s = kt % 3;
        if (kt + 1 < 8) { CP_WAIT1(); } else { CP_WAIT0(); }
        __syncthreads();
        if (kt + 2 < 8) { FILL((kt + 2) % 3, kt + 2); CP_COMMIT(); }
        COMPUTE(s);
    }

    float* C = g_corr + (size_t)bt * 512 * 1024;
    int mrow = n0 + wm * 64 + (lane >> 2);
    int cbase = hw0 + wn * 32 + 2 * (lane & 3);
#pragma unroll
    for (int mt = 0; mt < 4; mt++) {
#pragma unroll
        for (int nt = 0; nt < 4; nt++) {
            int col = cbase + nt * 8;
            int r0 = mrow + mt * 16;
            float2 o0, o1;
            o0.x = acc[mt][nt][0] * 0.0625f;
            o0.y = acc[mt][nt][1] * 0.0625f;
            o1.x = acc[mt][nt][2] * 0.0625f;
            o1.y = acc[mt][nt][3] * 0.0625f;
            *reinterpret_cast<float2*>(C + (size_t)r0 * 1024 + col) = o0;
            *reinterpret_cast<float2*>(C + (size_t)(r0 + 8) * 1024 + col) = o1;
        }
    }
}

// ---------------------------------------------------------------------------
// Bilinear feature sampling; writes q as bf16 hi/lo.
// ---------------------------------------------------------------------------
__global__ void __launch_bounds__(256) sample_kernel(const float* __restrict__ qp)
{
    int bn = blockIdx.x;
    float q0 = qp[bn * 3 + 0];
    float q1 = qp[bn * 3 + 1];
    float q2 = qp[bn * 3 + 2];

    int t = (int)(q0 * 23.0f);
    t = min(max(t, 0), 23);
    float yf = q1 * 31.0f;
    float xf = q2 * 31.0f;
    int y0 = min(max((int)floorf(yf), 0), 31);
    int y1 = min(y0 + 1, 31);
    int x0 = min(max((int)floorf(xf), 0), 31);
    int x1 = min(x0 + 1, 31);
    float wy1 = yf - (float)y0, wy0 = 1.0f - wy1;
    float wx1 = xf - (float)x0, wx0 = 1.0f - wx1;

    int b = bn >> 9;
    const float* f = g_feat3 + (size_t)(b * 24 + t) * 1024 * 256;
    int c = threadIdx.x;
    float f00 = f[(size_t)(y0 * 32 + x0) * 256 + c];
    float f01 = f[(size_t)(y0 * 32 + x1) * 256 + c];
    float f10 = f[(size_t)(y1 * 32 + x0) * 256 + c];
    float f11 = f[(size_t)(y1 * 32 + x1) * 256 + c];
    float f0 = f00 * wx0 + f01 * wx1;
    float f1 = f10 * wx0 + f11 * wx1;
    float v = f0 * wy0 + f1 * wy1;
    __nv_bfloat16 hb = __float2bfloat16(v);
    g_qh[(size_t)bn * 256 + c] = hb;
    g_ql[(size_t)bn * 256 + c] = __float2bfloat16(v - __bfloat162float(hb));
}

// ---------------------------------------------------------------------------
// Fused softmax(corr*10) expectation + occlusion.
// ---------------------------------------------------------------------------
__global__ void __launch_bounds__(256) finalize_kernel(float* __restrict__ out)
{
    int gwarp = (blockIdx.x * 256 + threadIdx.x) >> 5;
    int lane  = threadIdx.x & 31;

    const float* c = g_corr + (size_t)gwarp * 1024;
    float v[32];
    float m = -1e30f;
#pragma unroll
    for (int i = 0; i < 8; i++) {
        float4 t4 = *reinterpret_cast<const float4*>(&c[i * 128 + lane * 4]);
        v[i * 4 + 0] = t4.x;
        v[i * 4 + 1] = t4.y;
        v[i * 4 + 2] = t4.z;
        v[i * 4 + 3] = t4.w;
        m = fmaxf(m, fmaxf(fmaxf(t4.x, t4.y), fmaxf(t4.z, t4.w)));
    }
#pragma unroll
    for (int o = 16; o > 0; o >>= 1)
        m = fmaxf(m, __shfl_xor_sync(0xffffffffu, m, o));

    float s = 0.0f, sx = 0.0f, sy = 0.0f;
#pragma unroll
    for (int i = 0; i < 8; i++) {
#pragma unroll
        for (int j = 0; j < 4; j++) {
            int idx = i * 128 + lane * 4 + j;
            float e = __expf(10.0f * (v[i * 4 + j] - m));
            s  += e;
            sx += e * (float)(idx & 31);
            sy += e * (float)(idx >> 5);
        }
    }
#pragma unroll
    for (int o = 16; o > 0; o >>= 1) {
        s  += __shfl_xor_sync(0xffffffffu, s, o);
        sx += __shfl_xor_sync(0xffffffffu, sx, o);
        sy += __shfl_xor_sync(0xffffffffu, sy, o);
    }

    if (lane == 0) {
        int bt = gwarp >> 9;
        int n  = gwarp & 511;
        int b  = bt / 24;
        int t  = bt - b * 24;
        int o  = (b * 512 + n) * 24 + t;
        float inv = 8.0f / s;
        out[2 * o + 0] = sx * inv;
        out[2 * o + 1] = sy * inv;
        out[2 * 24576 + o] = 1.0f / (1.0f + __expf(m));
    }
}

// ---------------------------------------------------------------------------
// Launch
// ---------------------------------------------------------------------------
extern "C" void kernel_launch(void* const* d_in, const int* in_sizes, int n_in,
                              void* d_out, int out_size)
{
    const float* video = (const float*)d_in[0];
    const float* qp    = (const float*)d_in[1];
    const float* w1    = (const float*)d_in[2];
    const float* b1    = (const float*)d_in[3];
    const float* w2    = (const float*)d_in[4];
    const float* b2    = (const float*)d_in[5];
    const float* w3    = (const float*)d_in[6];
    const float* b3    = (const float*)d_in[7];

    __nv_bfloat16 *f1h, *f1l, *f2h, *f2l, *f3h, *f3l;
    __nv_bfloat16 *wt2h, *wt2l, *wt3h, *wt3l;
    float *f3;
    cudaGetSymbolAddress((void**)&f1h, g_f1h);
    cudaGetSymbolAddress((void**)&f1l, g_f1l);
    cudaGetSymbolAddress((void**)&f2h, g_f2h);
    cudaGetSymbolAddress((void**)&f2l, g_f2l);
    cudaGetSymbolAddress((void**)&f3,  g_feat3);
    cudaGetSymbolAddress((void**)&f3h, g_f3h);
    cudaGetSymbolAddress((void**)&f3l, g_f3l);
    cudaGetSymbolAddress((void**)&wt2h, g_wt2h);
    cudaGetSymbolAddress((void**)&wt2l, g_wt2l);
    cudaGetSymbolAddress((void**)&wt3h, g_wt3h);
    cudaGetSymbolAddress((void**)&wt3l, g_wt3l);

    cudaFuncSetAttribute(
        (const void*)conv_mma_kernel<64, 128, 128, 128, 64, 64, false>,
        cudaFuncAttributeMaxDynamicSharedMemorySize, DSMEM3);
    cudaFuncSetAttribute(
        (const void*)conv_mma_kernel<128, 256, 64, 64, 32, 32, true>,
        cudaFuncAttributeMaxDynamicSharedMemorySize, DSMEM3);
    cudaFuncSetAttribute((const void*)corr_mma_kernel,
                         cudaFuncAttributeMaxDynamicSharedMemorySize, DSMEM3);

    // weight transposes + bf16 split (tiny)
    transpose_split_w<<<(576 * 128 + 255) / 256, 256>>>(w2, wt2h, wt2l, 576, 128);
    transpose_split_w<<<(1152 * 256 + 255) / 256, 256>>>(w3, wt3h, wt3l, 1152, 256);

    // conv1: fp32 direct, epilogue splits to bf16 hi/lo
    conv1_kernel<<<6144, 128>>>(video, w1, b1);

    // conv2: 196608 px / 128 = 1536 tiles
    conv_mma_kernel<64, 128, 128, 128, 64, 64, false>
        <<<dim3(1536, 1, 1), 256, DSMEM3>>>(f1h, f1l, wt2h, wt2l, b2,
                                            f2h, f2l, nullptr);

    // conv3: 49152 px / 128 = 384 tiles, 2 N-chunks; writes fp32 + hi/lo
    conv_mma_kernel<128, 256, 64, 64, 32, 32, true>
        <<<dim3(384, 2, 1), 256, DSMEM3>>>(f2h, f2l, wt3h, wt3l, b3,
                                           f3h, f3l, f3);

    // feature sampling -> q bf16 hi/lo
    sample_kernel<<<1024, 256>>>(qp);

    // correlation GEMM: 8 hw-tiles x 4 n-tiles x 48 bt
    corr_mma_kernel<<<dim3(8, 4, 48), 256, DSMEM3>>>();

    // softmax + expectation + occlusion
    finalize_kernel<<<3072, 256>>>((float*)d_out);
}